// round 13
// baseline (speedup 1.0000x reference)
#include <cuda_runtime.h>
#include <cstddef>
#include <cstdint>

#define NNODE 10000
#define NEDGE 160000

// ---------------- scratch (static device globals; no allocation) ----------------
__device__ float g_h[NEDGE * 64];            // fc hidden (after layer 2)
__device__ float g_w[NEDGE * 512];           // edge weights w = h @ fc_w2 / 8
__device__ float g_ys[NNODE * 128];          // y_s
__device__ float g_yvt[3 * NNODE * 128];     // y_v, [c][n][u]
__device__ float g_scs[NNODE * 128];         // sc_s
__device__ float g_scvt[3 * NNODE * 128];    // sc_v, [c][n][w]
__device__ float g_aggs[NNODE * 256];        // aggregated s (pre lin2)
__device__ float g_aggvt[3 * NNODE * 256];   // aggregated v, [c][n][p]
__device__ int   g_cnt[NNODE];
__device__ int   g_pos[NNODE];
__device__ int   g_rowstart[NNODE + 1];
__device__ int   g_eid[NEDGE];

#define L1S_C  0.08838834764831845f    // 1/sqrt(128)
#define SCN_C  0.027950849718747373f   // 1/sqrt(1280)
#define OUTA_C 0.015625f               // (1/sqrt(16)) * (1/sqrt(256))

// ================= mma.sync tf32 helpers (plain sm_103-legal) ===================
__device__ __forceinline__ void tf32_split(float x, uint32_t& big, uint32_t& sml)
{
    uint32_t b;
    asm("cvt.rna.tf32.f32 %0, %1;" : "=r"(b) : "f"(x));
    float r = x - __uint_as_float(b);
    uint32_t s;
    asm("cvt.rna.tf32.f32 %0, %1;" : "=r"(s) : "f"(r));
    big = b; sml = s;
}
__device__ __forceinline__ void mma_tf32(float* c, const uint32_t* a,
                                         const uint32_t* b)
{
    asm volatile(
        "mma.sync.aligned.m16n8k8.row.col.f32.tf32.tf32.f32 "
        "{%0,%1,%2,%3}, {%4,%5,%6,%7}, {%8,%9}, {%0,%1,%2,%3};"
        : "+f"(c[0]), "+f"(c[1]), "+f"(c[2]), "+f"(c[3])
        : "r"(a[0]), "r"(a[1]), "r"(a[2]), "r"(a[3]), "r"(b[0]), "r"(b[1]));
}

// ---------------- tensor-core w-GEMM: g_w = (g_h @ fc_w2) / 8 -------------------
// 128x128 block tile, 8 warps (2x4), warp tile 64x32, K=64, 3xTF32 split.
// Smem strides 68/136: both fragment load patterns hit all 32 banks once.
#define SA 68
#define SB 136
#define WTC_SMEM ((128 * SA + 64 * SB) * 4)

__global__ void __launch_bounds__(256) k_wtc(const float* __restrict__ fcw2)
{
    extern __shared__ float smw[];
    float* As = smw;                 // [128][SA]
    float* Bs = smw + 128 * SA;      // [64][SB]
    const int tid = threadIdx.x;
    const int e0 = blockIdx.y * 128;
    const int n0 = blockIdx.x * 128;

    // stage A: 128 edges x 64 K (contiguous in g_h)
    const float4* A4 = (const float4*)(g_h + (size_t)e0 * 64);
#pragma unroll
    for (int i = 0; i < 8; ++i) {
        int idx = i * 256 + tid;            // 0..2047
        int r = idx >> 4, c4 = (idx & 15) * 4;
        float4 v = __ldg(A4 + idx);
        *(float4*)&As[r * SA + c4] = v;
    }
    // stage B: 64 K x 128 N slice of fc_w2 (row-major 64x512)
#pragma unroll
    for (int i = 0; i < 8; ++i) {
        int idx = i * 256 + tid;            // 0..2047
        int k = idx >> 5, n4 = (idx & 31) * 4;
        float4 v = __ldg((const float4*)(fcw2 + (size_t)k * 512 + n0) + (idx & 31));
        *(float4*)&Bs[k * SB + n4] = v;
    }
    __syncthreads();

    const int warp = tid >> 5, lane = tid & 31;
    const int wm = (warp >> 2) * 64;        // 0 / 64
    const int wn = (warp & 3) * 32;         // 0..96
    const int grp = lane >> 2, qid = lane & 3;

    float acc[4][4][4];
#pragma unroll
    for (int mi = 0; mi < 4; ++mi)
#pragma unroll
        for (int ni = 0; ni < 4; ++ni)
#pragma unroll
            for (int j = 0; j < 4; ++j) acc[mi][ni][j] = 0.f;

#pragma unroll
    for (int kb = 0; kb < 64; kb += 8) {
        uint32_t abig[4][4], asml[4][4];
#pragma unroll
        for (int mi = 0; mi < 4; ++mi) {
            int r0 = wm + mi * 16 + grp;
            tf32_split(As[r0 * SA + kb + qid],           abig[mi][0], asml[mi][0]);
            tf32_split(As[(r0 + 8) * SA + kb + qid],     abig[mi][1], asml[mi][1]);
            tf32_split(As[r0 * SA + kb + qid + 4],       abig[mi][2], asml[mi][2]);
            tf32_split(As[(r0 + 8) * SA + kb + qid + 4], abig[mi][3], asml[mi][3]);
        }
        uint32_t bbig[4][2], bsml[4][2];
#pragma unroll
        for (int ni = 0; ni < 4; ++ni) {
            int nb = wn + ni * 8 + grp;
            tf32_split(Bs[(kb + qid) * SB + nb],     bbig[ni][0], bsml[ni][0]);
            tf32_split(Bs[(kb + qid + 4) * SB + nb], bbig[ni][1], bsml[ni][1]);
        }
#pragma unroll
        for (int mi = 0; mi < 4; ++mi)
#pragma unroll
            for (int ni = 0; ni < 4; ++ni) {
                mma_tf32(acc[mi][ni], abig[mi], bbig[ni]);
                mma_tf32(acc[mi][ni], abig[mi], bsml[ni]);
                mma_tf32(acc[mi][ni], asml[mi], bbig[ni]);
            }
    }

    // epilogue: scale by 1/8, write float2 pairs
#pragma unroll
    for (int mi = 0; mi < 4; ++mi) {
#pragma unroll
        for (int ni = 0; ni < 4; ++ni) {
            int m = e0 + wm + mi * 16 + grp;
            int n = n0 + wn + ni * 8 + qid * 2;
            float2 lo = make_float2(0.125f * acc[mi][ni][0],
                                    0.125f * acc[mi][ni][1]);
            float2 hi = make_float2(0.125f * acc[mi][ni][2],
                                    0.125f * acc[mi][ni][3]);
            *(float2*)(g_w + (size_t)m * 512 + n)       = lo;
            *(float2*)(g_w + (size_t)(m + 8) * 512 + n) = hi;
        }
    }
}

// ---------------- SGEMM body, C = alpha * A@B (+ D) ----------------------------
// BM=BN=128, BK=8, 256 threads, 8x8 microtile, plain FFMA (proven path).
template <int AMODE, int OMODE>
__device__ __forceinline__ void sgemm_body(
    float (*As)[128], float (*Bs)[128],
    int bx, int by,
    const float* __restrict__ A, const float* __restrict__ B,
    float* __restrict__ C, const float* __restrict__ D,
    const float* __restrict__ attrs,
    int M, int K, int Ncols, int lda, float alpha)
{
    const int tid = threadIdx.x;
    const int bm = by * 128;
    const int bn = bx * 128;
    const int tx = tid & 15;
    const int ty = tid >> 4;
    const int row0 = ty * 8;
    const int col0 = tx * 8;

    const int kA  = tid & 7;
    const int mA0 = tid >> 3;      // + 32*s
    const int nB  = tid & 127;
    const int kB0 = tid >> 7;      // + 2*s

    int mg[4], an[4], ac[4];
#pragma unroll
    for (int s = 0; s < 4; ++s) {
        int m = bm + mA0 + 32 * s;
        mg[s] = m;
        if (AMODE >= 2) {
            int c = m / NNODE;
            an[s] = m - c * NNODE;
            ac[s] = c;
        } else {
            an[s] = m; ac[s] = 0;
        }
    }

    float acc[8][8];
#pragma unroll
    for (int i = 0; i < 8; ++i)
#pragma unroll
        for (int j = 0; j < 8; ++j) acc[i][j] = 0.f;

    for (int k0 = 0; k0 < K; k0 += 8) {
#pragma unroll
        for (int s = 0; s < 4; ++s) {
            int m = mg[s];
            int kk = k0 + kA;
            float v = 0.f;
            if (m < M) {
                if (AMODE == 0) {
                    v = __ldg(A + (size_t)m * lda + kk);
                } else if (AMODE == 1) {
                    int u = kk / 10, vv = kk - u * 10;
                    v = __ldg(A + (size_t)m * 512 + u) * __ldg(attrs + m * 10 + vv);
                } else if (AMODE == 2) {
                    int u = kk / 10, vv = kk - u * 10;
                    v = __ldg(A + (size_t)an[s] * 512 + 128 + u * 3 + ac[s]) *
                        __ldg(attrs + an[s] * 10 + vv);
                } else {
                    v = __ldg(A + (size_t)an[s] * 512 + 128 + kk * 3 + ac[s]);
                }
            }
            As[kA][mA0 + 32 * s] = v;
        }
#pragma unroll
        for (int s = 0; s < 4; ++s) {
            int kk = kB0 + 2 * s;
            Bs[kk][nB] = __ldg(B + (size_t)(k0 + kk) * Ncols + bn + nB);
        }
        __syncthreads();
#pragma unroll
        for (int k = 0; k < 8; ++k) {
            float4 a0 = *(const float4*)&As[k][row0];
            float4 a1 = *(const float4*)&As[k][row0 + 4];
            float4 b0 = *(const float4*)&Bs[k][col0];
            float4 b1 = *(const float4*)&Bs[k][col0 + 4];
            float a[8] = {a0.x, a0.y, a0.z, a0.w, a1.x, a1.y, a1.z, a1.w};
            float b[8] = {b0.x, b0.y, b0.z, b0.w, b1.x, b1.y, b1.z, b1.w};
#pragma unroll
            for (int i = 0; i < 8; ++i)
#pragma unroll
                for (int j = 0; j < 8; ++j)
                    acc[i][j] = fmaf(a[i], b[j], acc[i][j]);
        }
        __syncthreads();
    }

#pragma unroll
    for (int i = 0; i < 8; ++i) {
        int m = bm + row0 + i;
        if (m >= M) continue;
        float r[8];
#pragma unroll
        for (int j = 0; j < 8; ++j) r[j] = alpha * acc[i][j];
        if (D) {
            size_t doff = (size_t)m * Ncols + bn + col0;
            float4 d0 = __ldg((const float4*)(D + doff));
            float4 d1 = __ldg((const float4*)(D + doff + 4));
            r[0] += d0.x; r[1] += d0.y; r[2] += d0.z; r[3] += d0.w;
            r[4] += d1.x; r[5] += d1.y; r[6] += d1.z; r[7] += d1.w;
        }
        if (OMODE == 0) {
            size_t off = (size_t)m * Ncols + bn + col0;
            *(float4*)(C + off)     = make_float4(r[0], r[1], r[2], r[3]);
            *(float4*)(C + off + 4) = make_float4(r[4], r[5], r[6], r[7]);
        } else if (OMODE == 1) {
            float* base = C + (size_t)m * 512 + bn + col0;
            *(float4*)(base)     = make_float4(r[0], r[1], r[2], r[3]);
            *(float4*)(base + 4) = make_float4(r[4], r[5], r[6], r[7]);
        } else {
            int c = m / NNODE;
            int n = m - c * NNODE;
            float* base = C + (size_t)n * 512 + 128 + (size_t)(bn + col0) * 3 + c;
#pragma unroll
            for (int j = 0; j < 8; ++j) base[j * 3] = r[j];
        }
    }
}

// mega1: sc einsums + lin1 (w-GEMM moved to tensor cores). Long-K first (LPT).
__global__ void __launch_bounds__(256) k_mega1(
    const float* __restrict__ nf, const float* __restrict__ attrs,
    const float* __restrict__ l1s, const float* __restrict__ l1v,
    const float* __restrict__ scw_s, const float* __restrict__ scw_v)
{
    __shared__ __align__(16) float As[8][128];
    __shared__ __align__(16) float Bs[8][128];
    int b = blockIdx.x;
    if (b < 79) {
        sgemm_body<1, 0>(As, Bs, 0, b, nf, scw_s, g_scs, nullptr, attrs,
                         NNODE, 1280, 128, 0, SCN_C);
    } else if (b < 314) {
        sgemm_body<2, 0>(As, Bs, 0, b - 79, nf, scw_v, g_scvt, nullptr, attrs,
                         3 * NNODE, 1280, 128, 0, SCN_C);
    } else if (b < 393) {
        sgemm_body<0, 0>(As, Bs, 0, b - 314, nf, l1s, g_ys, nullptr, nullptr,
                         NNODE, 128, 128, 512, L1S_C);
    } else {
        sgemm_body<3, 0>(As, Bs, 0, b - 393, nf, l1v, g_yvt, nullptr, nullptr,
                         3 * NNODE, 128, 128, 0, L1S_C);
    }
}

// mega2: lin2 (s and v) with skip-connection, writing the packed output directly.
__global__ void __launch_bounds__(256) k_mega2(
    const float* __restrict__ l2s, const float* __restrict__ l2v,
    float* __restrict__ out)
{
    __shared__ __align__(16) float As[8][128];
    __shared__ __align__(16) float Bs[8][128];
    int b = blockIdx.x;
    if (b < 79) {
        sgemm_body<0, 1>(As, Bs, 0, b, g_aggs, l2s, out, g_scs, nullptr,
                         NNODE, 256, 128, 256, OUTA_C);
    } else {
        sgemm_body<0, 2>(As, Bs, 0, b - 79, g_aggvt, l2v, out, g_scvt, nullptr,
                         3 * NNODE, 256, 128, 256, OUTA_C);
    }
}

// ---------------- fc layers 0+1 (8->64->64, scaled SiLU, 1 MUFU per silu) ------
__device__ __forceinline__ float siluc(float x)
{
    float xc = fmaxf(x, -20.0f);
    float e = __expf(-xc);                 // 1 MUFU (EX2)
    float y = 1.0f + e;
    float r = __uint_as_float(0x7EF311C3u - __float_as_uint(y));  // rcp seed
    r = r * (2.0f - y * r);
    r = r * (2.0f - y * r);
    r = r * (2.0f - y * r);
    return 1.679f * x * r;
}

__global__ void __launch_bounds__(128) k_fc01(
    const float* __restrict__ ef, const float* __restrict__ w0,
    const float* __restrict__ w1)
{
    __shared__ __align__(16) float w0s[8 * 64];
    __shared__ __align__(16) float w1s[64 * 64];
    __shared__ float efs[64][9];
    __shared__ float h0s[64][66];
    const int tid = threadIdx.x;
    const float rs8 = 0.35355339059327373f;
    for (int i = tid; i < 8 * 64; i += 128) w0s[i] = w0[i] * rs8;
    for (int i = tid; i < 1024; i += 128) {
        float4 v = __ldg((const float4*)w1 + i);
        v.x *= 0.125f; v.y *= 0.125f; v.z *= 0.125f; v.w *= 0.125f;
        *(float4*)&w1s[i * 4] = v;
    }
    const int e0 = blockIdx.x * 64;
    {
        float4 v = __ldg((const float4*)(ef + (size_t)e0 * 8) + tid);
        int e = tid >> 1, k4 = (tid & 1) * 4;
        efs[e][k4 + 0] = v.x; efs[e][k4 + 1] = v.y;
        efs[e][k4 + 2] = v.z; efs[e][k4 + 3] = v.w;
    }
    __syncthreads();

    const int warp = tid >> 5, lane = tid & 31;
    const int j8 = (lane & 7) * 8;
    const int es = warp * 4 + (lane >> 3);
    const int eb = es * 4;

    float acc[4][8];
#pragma unroll
    for (int i = 0; i < 4; ++i)
#pragma unroll
        for (int j = 0; j < 8; ++j) acc[i][j] = 0.f;
#pragma unroll
    for (int k = 0; k < 8; ++k) {
        float4 wA = *(const float4*)&w0s[k * 64 + j8];
        float4 wB = *(const float4*)&w0s[k * 64 + j8 + 4];
        float wv[8] = {wA.x, wA.y, wA.z, wA.w, wB.x, wB.y, wB.z, wB.w};
#pragma unroll
        for (int i = 0; i < 4; ++i) {
            float a = efs[eb + i][k];
#pragma unroll
            for (int j = 0; j < 8; ++j) acc[i][j] = fmaf(a, wv[j], acc[i][j]);
        }
    }
#pragma unroll
    for (int i = 0; i < 4; ++i) {
#pragma unroll
        for (int j = 0; j < 8; j += 2) {
            float2 p = make_float2(siluc(acc[i][j]), siluc(acc[i][j + 1]));
            *(float2*)&h0s[eb + i][j8 + j] = p;
        }
    }
    __syncthreads();

#pragma unroll
    for (int i = 0; i < 4; ++i)
#pragma unroll
        for (int j = 0; j < 8; ++j) acc[i][j] = 0.f;
#pragma unroll 8
    for (int k = 0; k < 64; ++k) {
        float4 wA = *(const float4*)&w1s[k * 64 + j8];
        float4 wB = *(const float4*)&w1s[k * 64 + j8 + 4];
        float wv[8] = {wA.x, wA.y, wA.z, wA.w, wB.x, wB.y, wB.z, wB.w};
#pragma unroll
        for (int i = 0; i < 4; ++i) {
            float a = h0s[eb + i][k];
#pragma unroll
            for (int j = 0; j < 8; ++j) acc[i][j] = fmaf(a, wv[j], acc[i][j]);
        }
    }
#pragma unroll
    for (int i = 0; i < 4; ++i) {
        float o[8];
#pragma unroll
        for (int j = 0; j < 8; ++j) o[j] = siluc(acc[i][j]);
        float* dst = g_h + (size_t)(e0 + eb + i) * 64 + j8;
        *(float4*)(dst)     = make_float4(o[0], o[1], o[2], o[3]);
        *(float4*)(dst + 4) = make_float4(o[4], o[5], o[6], o[7]);
    }
}

// ---------------- CSR build ----------------------------------------------------
__global__ void k_count(const int* __restrict__ ei)
{
    int e = blockIdx.x * 256 + threadIdx.x;
    if (e < NEDGE) atomicAdd(&g_cnt[ei[e]], 1);
}

__global__ void k_scan()
{
    __shared__ int sm[256];
    const int tid = threadIdx.x;
    const int CH = (NNODE + 255) / 256;
    int beg = tid * CH;
    int end = min(beg + CH, NNODE);
    int s = 0;
    for (int i = beg; i < end; ++i) s += g_cnt[i];
    sm[tid] = s;
    __syncthreads();
    for (int off = 1; off < 256; off <<= 1) {
        int v = 0;
        if (tid >= off) v = sm[tid - off];
        __syncthreads();
        sm[tid] += v;
        __syncthreads();
    }
    int run = sm[tid] - s;
    for (int i = beg; i < end; ++i) {
        g_rowstart[i] = run;
        g_pos[i] = run;
        run += g_cnt[i];
    }
    if (tid == 255) g_rowstart[NNODE] = sm[255];
}

__global__ void k_fill(const int* __restrict__ ei)
{
    int e = blockIdx.x * 256 + threadIdx.x;
    if (e < NEDGE) {
        int d = ei[e];
        int p = atomicAdd(&g_pos[d], 1);
        g_eid[p] = e;
    }
}

// ---------------- message + aggregation: one warp per node, no float atomics ---
__global__ void __launch_bounds__(256) k_agg(const int* __restrict__ ei,
                                             const float* __restrict__ eattr)
{
    int gw = (blockIdx.x * blockDim.x + threadIdx.x) >> 5;
    int lane = threadIdx.x & 31;
    if (gw >= NNODE) return;
    const int n = gw;
    const int u0 = lane * 4;
    const float inv_sq3 = 0.5773502691896258f;

    float s0[4] = {0, 0, 0, 0}, s1[4] = {0, 0, 0, 0};
    float v2[3][4] = {{0}}, v3[3][4] = {{0}};

    const int beg = g_rowstart[n];
    const int end = g_rowstart[n + 1];
    for (int i = beg; i < end; ++i) {
        int e = g_eid[i];
        float4 ea = __ldg((const float4*)(eattr + (size_t)e * 4));
        int s = ei[NEDGE + e];  // src = edge_index[1]
        const float* wr = g_w + (size_t)e * 512 + u0;
        float4 wss = __ldg((const float4*)(wr));
        float4 wsv = __ldg((const float4*)(wr + 128));
        float4 wvs = __ldg((const float4*)(wr + 256));
        float4 wvv = __ldg((const float4*)(wr + 384));
        const float* yb = g_ys + (size_t)s * 128 + u0;
        float4 xs = __ldg((const float4*)(yb));
        const float* vb = g_yvt + (size_t)s * 128 + u0;
        float4 x0 = __ldg((const float4*)(vb));
        float4 x1 = __ldg((const float4*)(vb + NNODE * 128));
        float4 x2 = __ldg((const float4*)(vb + 2 * NNODE * 128));

        float as_ = ea.x, av0 = ea.y, av1 = ea.z, av2 = ea.w;
        float WSS[4] = {wss.x, wss.y, wss.z, wss.w};
        float WSV[4] = {wsv.x, wsv.y, wsv.z, wsv.w};
        float WVS[4] = {wvs.x, wvs.y, wvs.z, wvs.w};
        float WVV[4] = {wvv.x, wvv.y, wvv.z, wvv.w};
        float XS[4]  = {xs.x, xs.y, xs.z, xs.w};
        float X0[4]  = {x0.x, x0.y, x0.z, x0.w};
        float X1[4]  = {x1.x, x1.y, x1.z, x1.w};
        float X2[4]  = {x2.x, x2.y, x2.z, x2.w};
#pragma unroll
        for (int t = 0; t < 4; ++t) {
            s0[t] = fmaf(WSS[t] * as_, XS[t], s0[t]);
            float dot = X0[t] * av0 + X1[t] * av1 + X2[t] * av2;
            s1[t] = fmaf(WVV[t] * inv_sq3, dot, s1[t]);
            float tsv = WSV[t] * XS[t];
            v2[0][t] = fmaf(tsv, av0, v2[0][t]);
            v2[1][t] = fmaf(tsv, av1, v2[1][t]);
            v2[2][t] = fmaf(tsv, av2, v2[2][t]);
            float tvs = WVS[t] * as_;
            v3[0][t] = fmaf(tvs, X0[t], v3[0][t]);
            v3[1][t] = fmaf(tvs, X1[t], v3[1][t]);
            v3[2][t] = fmaf(tvs, X2[t], v3[2][t]);
        }
    }

    float* sp = g_aggs + (size_t)n * 256 + u0;
    *(float4*)(sp)       = make_float4(s0[0], s0[1], s0[2], s0[3]);
    *(float4*)(sp + 128) = make_float4(s1[0], s1[1], s1[2], s1[3]);
#pragma unroll
    for (int c = 0; c < 3; ++c) {
        float* vp = g_aggvt + (size_t)c * NNODE * 256 + (size_t)n * 256 + u0;
        *(float4*)(vp)       = make_float4(v2[c][0], v2[c][1], v2[c][2], v2[c][3]);
        *(float4*)(vp + 128) = make_float4(v3[c][0], v3[c][1], v3[c][2], v3[c][3]);
    }
}

// ---------------- launch -------------------------------------------------------
extern "C" void kernel_launch(void* const* d_in, const int* in_sizes, int n_in,
                              void* d_out, int out_size)
{
    const float* node_feats = (const float*)d_in[0];
    const float* node_attrs = (const float*)d_in[1];
    const float* edge_feats = (const float*)d_in[2];
    const float* edge_attrs = (const float*)d_in[3];
    const int*   edge_index = (const int*)d_in[4];
    const float* lin1_ws = (const float*)d_in[5];
    const float* lin1_wv = (const float*)d_in[6];
    const float* fc_w0   = (const float*)d_in[7];
    const float* fc_w1   = (const float*)d_in[8];
    const float* fc_w2   = (const float*)d_in[9];
    const float* lin2_ws = (const float*)d_in[10];
    const float* lin2_wv = (const float*)d_in[11];
    const float* sc_ws   = (const float*)d_in[12];
    const float* sc_wv   = (const float*)d_in[13];
    float* out = (float*)d_out;

    int* p_cnt;
    cudaGetSymbolAddress((void**)&p_cnt, g_cnt);
    cudaFuncSetAttribute(k_wtc, cudaFuncAttributeMaxDynamicSharedMemorySize,
                         WTC_SMEM);

    // CSR build
    cudaMemsetAsync(p_cnt, 0, NNODE * sizeof(int));
    k_count<<<625, 256>>>(edge_index);
    k_scan<<<1, 256>>>();
    k_fill<<<625, 256>>>(edge_index);

    // fc small layers -> g_h
    k_fc01<<<2500, 128>>>(edge_feats, fc_w0, fc_w1);

    // sc + lin1 GEMMs (FFMA path): [0,79) sc_s | [79,314) sc_v | [314,393) y_s |
    // [393,628) y_v
    k_mega1<<<628, 256>>>(node_feats, node_attrs, lin1_ws, lin1_wv, sc_ws, sc_wv);

    // w = h @ fc_w2 / 8 on mma.sync tf32 (3xTF32 split, ~fp32 accuracy)
    k_wtc<<<dim3(4, 1250), 256, WTC_SMEM>>>(fc_w2);

    // messages + segment sum (CSR, warp per node, register accumulators)
    k_agg<<<1250, 256>>>(edge_index, edge_attrs);

    // lin2 (s + v) + skip connection, writing packed output directly
    k_mega2<<<314, 256>>>(lin2_ws, lin2_wv, out);
}

// round 14
// speedup vs baseline: 1.0124x; 1.0124x over previous
#include <cuda_runtime.h>
#include <cstddef>

#define NNODE 10000
#define NEDGE 160000

// ---------------- scratch (static device globals; no allocation) ----------------
__device__ float g_h[NEDGE * 64];            // fc hidden (after layer 2)
__device__ float g_w[NEDGE * 512];           // edge weights w = h @ fc_w2 / 8
__device__ float g_ys[NNODE * 128];          // y_s
__device__ float g_yvt[3 * NNODE * 128];     // y_v, [c][n][u]
__device__ float g_scs[NNODE * 128];         // sc_s
__device__ float g_scvt[3 * NNODE * 128];    // sc_v, [c][n][w]
__device__ float g_aggs[NNODE * 256];        // aggregated s (pre lin2)
__device__ float g_aggvt[3 * NNODE * 256];   // aggregated v, [c][n][p]
__device__ int   g_cnt[NNODE];
__device__ int   g_pos[NNODE];
__device__ int   g_rowstart[NNODE + 1];
__device__ int   g_eid[NEDGE];

#define L1S_C  0.08838834764831845f    // 1/sqrt(128)
#define SCN_C  0.027950849718747373f   // 1/sqrt(1280)
#define OUTA_C 0.015625f               // (1/sqrt(16)) * (1/sqrt(256))

// ---------------- A-element loader (templated synthesized views) ----------------
// AMODE 0: A[m*lda + k]
// AMODE 1: Z_s: node_feats[m*512 + k/10] * attrs[m*10 + k%10]
// AMODE 2: Z_v: rows m=(c*NNODE+n): node_feats[n*512+128+(k/10)*3+c]*attrs[n*10+k%10]
// AMODE 3: x_v: rows m=(c*NNODE+n): node_feats[n*512+128+k*3+c]
template <int AMODE>
__device__ __forceinline__ float loadA_elem(
    const float* __restrict__ A, const float* __restrict__ attrs,
    int m, int an, int ac, int kk, int lda, int M)
{
    if (m >= M) return 0.f;
    if (AMODE == 0) {
        return __ldg(A + (size_t)m * lda + kk);
    } else if (AMODE == 1) {
        int u = kk / 10, vv = kk - u * 10;
        return __ldg(A + (size_t)m * 512 + u) * __ldg(attrs + m * 10 + vv);
    } else if (AMODE == 2) {
        int u = kk / 10, vv = kk - u * 10;
        return __ldg(A + (size_t)an * 512 + 128 + u * 3 + ac) *
               __ldg(attrs + an * 10 + vv);
    } else {
        return __ldg(A + (size_t)an * 512 + 128 + kk * 3 + ac);
    }
}

// ---------------- SGEMM body, C = alpha * A@B (+ D) ----------------------------
// BM=BN=128, BK=8, 256 threads, 8x8 microtile, register-staged software pipeline:
// next k-tile's global loads are issued right after the barrier so their latency
// overlaps the 64-FMA inner section.
// OMODE 0: C[m*Ncols + col]
// OMODE 1: C[m*512 + col]               (packed out, scalar part)
// OMODE 2: C[n*512 + 128 + col*3 + c]   (packed out, vector part; m=c*NNODE+n)
template <int AMODE, int OMODE>
__device__ __forceinline__ void sgemm_body(
    float (*As)[128], float (*Bs)[128],
    int bx, int by,
    const float* __restrict__ A, const float* __restrict__ B,
    float* __restrict__ C, const float* __restrict__ D,
    const float* __restrict__ attrs,
    int M, int K, int Ncols, int lda, float alpha)
{
    const int tid = threadIdx.x;
    const int bm = by * 128;
    const int bn = bx * 128;
    const int tx = tid & 15;
    const int ty = tid >> 4;
    const int row0 = ty * 8;
    const int col0 = tx * 8;

    const int kA  = tid & 7;
    const int mA0 = tid >> 3;      // + 32*s
    const int nB  = tid & 127;
    const int kB0 = tid >> 7;      // + 2*s

    int mg[4], an[4], ac[4];
#pragma unroll
    for (int s = 0; s < 4; ++s) {
        int m = bm + mA0 + 32 * s;
        mg[s] = m;
        if (AMODE >= 2) {
            int c = m / NNODE;
            an[s] = m - c * NNODE;
            ac[s] = c;
        } else {
            an[s] = m; ac[s] = 0;
        }
    }

    float acc[8][8];
#pragma unroll
    for (int i = 0; i < 8; ++i)
#pragma unroll
        for (int j = 0; j < 8; ++j) acc[i][j] = 0.f;

    // prologue: prefetch tile k0=0 into registers
    float vA[4], vB[4];
#pragma unroll
    for (int s = 0; s < 4; ++s)
        vA[s] = loadA_elem<AMODE>(A, attrs, mg[s], an[s], ac[s], kA, lda, M);
#pragma unroll
    for (int s = 0; s < 4; ++s)
        vB[s] = __ldg(B + (size_t)(kB0 + 2 * s) * Ncols + bn + nB);

    for (int k0 = 0; k0 < K; k0 += 8) {
#pragma unroll
        for (int s = 0; s < 4; ++s) As[kA][mA0 + 32 * s] = vA[s];
#pragma unroll
        for (int s = 0; s < 4; ++s) Bs[kB0 + 2 * s][nB] = vB[s];
        __syncthreads();

        if (k0 + 8 < K) {   // issue next tile's loads; latency hides under FMAs
            int kn = k0 + 8;
#pragma unroll
            for (int s = 0; s < 4; ++s)
                vA[s] = loadA_elem<AMODE>(A, attrs, mg[s], an[s], ac[s],
                                          kn + kA, lda, M);
#pragma unroll
            for (int s = 0; s < 4; ++s)
                vB[s] = __ldg(B + (size_t)(kn + kB0 + 2 * s) * Ncols + bn + nB);
        }

#pragma unroll
        for (int k = 0; k < 8; ++k) {
            float4 a0 = *(const float4*)&As[k][row0];
            float4 a1 = *(const float4*)&As[k][row0 + 4];
            float4 b0 = *(const float4*)&Bs[k][col0];
            float4 b1 = *(const float4*)&Bs[k][col0 + 4];
            float a[8] = {a0.x, a0.y, a0.z, a0.w, a1.x, a1.y, a1.z, a1.w};
            float b[8] = {b0.x, b0.y, b0.z, b0.w, b1.x, b1.y, b1.z, b1.w};
#pragma unroll
            for (int i = 0; i < 8; ++i)
#pragma unroll
                for (int j = 0; j < 8; ++j)
                    acc[i][j] = fmaf(a[i], b[j], acc[i][j]);
        }
        __syncthreads();
    }

#pragma unroll
    for (int i = 0; i < 8; ++i) {
        int m = bm + row0 + i;
        if (m >= M) continue;
        float r[8];
#pragma unroll
        for (int j = 0; j < 8; ++j) r[j] = alpha * acc[i][j];
        if (D) {
            size_t doff = (size_t)m * Ncols + bn + col0;
            float4 d0 = __ldg((const float4*)(D + doff));
            float4 d1 = __ldg((const float4*)(D + doff + 4));
            r[0] += d0.x; r[1] += d0.y; r[2] += d0.z; r[3] += d0.w;
            r[4] += d1.x; r[5] += d1.y; r[6] += d1.z; r[7] += d1.w;
        }
        if (OMODE == 0) {
            size_t off = (size_t)m * Ncols + bn + col0;
            *(float4*)(C + off)     = make_float4(r[0], r[1], r[2], r[3]);
            *(float4*)(C + off + 4) = make_float4(r[4], r[5], r[6], r[7]);
        } else if (OMODE == 1) {
            float* base = C + (size_t)m * 512 + bn + col0;
            *(float4*)(base)     = make_float4(r[0], r[1], r[2], r[3]);
            *(float4*)(base + 4) = make_float4(r[4], r[5], r[6], r[7]);
        } else {
            int c = m / NNODE;
            int n = m - c * NNODE;
            float* base = C + (size_t)n * 512 + 128 + (size_t)(bn + col0) * 3 + c;
#pragma unroll
            for (int j = 0; j < 8; ++j) base[j * 3] = r[j];
        }
    }
}

// ---------------- merged GEMM launches ------------------------------------------
// mega1: all GEMMs that depend only on fc hidden / inputs.
// Long-K sc jobs first (LPT), then lin1, then 5000 w-GEMM blocks fill the tail.
__global__ void __launch_bounds__(256) k_mega1(
    const float* __restrict__ nf, const float* __restrict__ attrs,
    const float* __restrict__ l1s, const float* __restrict__ l1v,
    const float* __restrict__ scw_s, const float* __restrict__ scw_v,
    const float* __restrict__ fcw2)
{
    __shared__ __align__(16) float As[8][128];
    __shared__ __align__(16) float Bs[8][128];
    int b = blockIdx.x;
    if (b < 79) {
        sgemm_body<1, 0>(As, Bs, 0, b, nf, scw_s, g_scs, nullptr, attrs,
                         NNODE, 1280, 128, 0, SCN_C);
    } else if (b < 314) {
        sgemm_body<2, 0>(As, Bs, 0, b - 79, nf, scw_v, g_scvt, nullptr, attrs,
                         3 * NNODE, 1280, 128, 0, SCN_C);
    } else if (b < 393) {
        sgemm_body<0, 0>(As, Bs, 0, b - 314, nf, l1s, g_ys, nullptr, nullptr,
                         NNODE, 128, 128, 512, L1S_C);
    } else if (b < 628) {
        sgemm_body<3, 0>(As, Bs, 0, b - 393, nf, l1v, g_yvt, nullptr, nullptr,
                         3 * NNODE, 128, 128, 0, L1S_C);
    } else {
        int l = b - 628;
        sgemm_body<0, 0>(As, Bs, l & 3, l >> 2, g_h, fcw2, g_w, nullptr, nullptr,
                         NEDGE, 64, 512, 64, 0.125f);
    }
}

// mega2: lin2 (s and v) with skip-connection, writing the packed output directly.
__global__ void __launch_bounds__(256) k_mega2(
    const float* __restrict__ l2s, const float* __restrict__ l2v,
    float* __restrict__ out)
{
    __shared__ __align__(16) float As[8][128];
    __shared__ __align__(16) float Bs[8][128];
    int b = blockIdx.x;
    if (b < 79) {
        sgemm_body<0, 1>(As, Bs, 0, b, g_aggs, l2s, out, g_scs, nullptr,
                         NNODE, 256, 128, 256, OUTA_C);
    } else {
        sgemm_body<0, 2>(As, Bs, 0, b - 79, g_aggvt, l2v, out, g_scvt, nullptr,
                         3 * NNODE, 256, 128, 256, OUTA_C);
    }
}

// ---------------- fc layers 0+1 (8->64->64, scaled SiLU, 1 MUFU per silu) ------
__device__ __forceinline__ float siluc(float x)
{
    float xc = fmaxf(x, -20.0f);
    float e = __expf(-xc);                 // 1 MUFU (EX2)
    float y = 1.0f + e;
    float r = __uint_as_float(0x7EF311C3u - __float_as_uint(y));  // rcp seed
    r = r * (2.0f - y * r);
    r = r * (2.0f - y * r);
    r = r * (2.0f - y * r);
    return 1.679f * x * r;
}

__global__ void __launch_bounds__(128) k_fc01(
    const float* __restrict__ ef, const float* __restrict__ w0,
    const float* __restrict__ w1)
{
    __shared__ __align__(16) float w0s[8 * 64];
    __shared__ __align__(16) float w1s[64 * 64];
    __shared__ float efs[64][9];
    __shared__ float h0s[64][66];
    const int tid = threadIdx.x;
    const float rs8 = 0.35355339059327373f;
    for (int i = tid; i < 8 * 64; i += 128) w0s[i] = w0[i] * rs8;
    for (int i = tid; i < 1024; i += 128) {
        float4 v = __ldg((const float4*)w1 + i);
        v.x *= 0.125f; v.y *= 0.125f; v.z *= 0.125f; v.w *= 0.125f;
        *(float4*)&w1s[i * 4] = v;
    }
    const int e0 = blockIdx.x * 64;
    {
        float4 v = __ldg((const float4*)(ef + (size_t)e0 * 8) + tid);
        int e = tid >> 1, k4 = (tid & 1) * 4;
        efs[e][k4 + 0] = v.x; efs[e][k4 + 1] = v.y;
        efs[e][k4 + 2] = v.z; efs[e][k4 + 3] = v.w;
    }
    __syncthreads();

    const int warp = tid >> 5, lane = tid & 31;
    const int j8 = (lane & 7) * 8;
    const int es = warp * 4 + (lane >> 3);
    const int eb = es * 4;

    float acc[4][8];
#pragma unroll
    for (int i = 0; i < 4; ++i)
#pragma unroll
        for (int j = 0; j < 8; ++j) acc[i][j] = 0.f;
#pragma unroll
    for (int k = 0; k < 8; ++k) {
        float4 wA = *(const float4*)&w0s[k * 64 + j8];
        float4 wB = *(const float4*)&w0s[k * 64 + j8 + 4];
        float wv[8] = {wA.x, wA.y, wA.z, wA.w, wB.x, wB.y, wB.z, wB.w};
#pragma unroll
        for (int i = 0; i < 4; ++i) {
            float a = efs[eb + i][k];
#pragma unroll
            for (int j = 0; j < 8; ++j) acc[i][j] = fmaf(a, wv[j], acc[i][j]);
        }
    }
#pragma unroll
    for (int i = 0; i < 4; ++i) {
#pragma unroll
        for (int j = 0; j < 8; j += 2) {
            float2 p = make_float2(siluc(acc[i][j]), siluc(acc[i][j + 1]));
            *(float2*)&h0s[eb + i][j8 + j] = p;
        }
    }
    __syncthreads();

#pragma unroll
    for (int i = 0; i < 4; ++i)
#pragma unroll
        for (int j = 0; j < 8; ++j) acc[i][j] = 0.f;
#pragma unroll 8
    for (int k = 0; k < 64; ++k) {
        float4 wA = *(const float4*)&w1s[k * 64 + j8];
        float4 wB = *(const float4*)&w1s[k * 64 + j8 + 4];
        float wv[8] = {wA.x, wA.y, wA.z, wA.w, wB.x, wB.y, wB.z, wB.w};
#pragma unroll
        for (int i = 0; i < 4; ++i) {
            float a = h0s[eb + i][k];
#pragma unroll
            for (int j = 0; j < 8; ++j) acc[i][j] = fmaf(a, wv[j], acc[i][j]);
        }
    }
#pragma unroll
    for (int i = 0; i < 4; ++i) {
        float o[8];
#pragma unroll
        for (int j = 0; j < 8; ++j) o[j] = siluc(acc[i][j]);
        float* dst = g_h + (size_t)(e0 + eb + i) * 64 + j8;
        *(float4*)(dst)     = make_float4(o[0], o[1], o[2], o[3]);
        *(float4*)(dst + 4) = make_float4(o[4], o[5], o[6], o[7]);
    }
}

// ---------------- CSR build ----------------------------------------------------
__global__ void k_count(const int* __restrict__ ei)
{
    int e = blockIdx.x * 256 + threadIdx.x;
    if (e < NEDGE) atomicAdd(&g_cnt[ei[e]], 1);
}

__global__ void k_scan()
{
    __shared__ int sm[256];
    const int tid = threadIdx.x;
    const int CH = (NNODE + 255) / 256;
    int beg = tid * CH;
    int end = min(beg + CH, NNODE);
    int s = 0;
    for (int i = beg; i < end; ++i) s += g_cnt[i];
    sm[tid] = s;
    __syncthreads();
    for (int off = 1; off < 256; off <<= 1) {
        int v = 0;
        if (tid >= off) v = sm[tid - off];
        __syncthreads();
        sm[tid] += v;
        __syncthreads();
    }
    int run = sm[tid] - s;
    for (int i = beg; i < end; ++i) {
        g_rowstart[i] = run;
        g_pos[i] = run;
        run += g_cnt[i];
    }
    if (tid == 255) g_rowstart[NNODE] = sm[255];
}

__global__ void k_fill(const int* __restrict__ ei)
{
    int e = blockIdx.x * 256 + threadIdx.x;
    if (e < NEDGE) {
        int d = ei[e];
        int p = atomicAdd(&g_pos[d], 1);
        g_eid[p] = e;
    }
}

// ---------------- message + aggregation: one warp per node, no float atomics ---
struct EdgeData {
    float4 ea, wss, wsv, wvs, wvv, xs, x0, x1, x2;
};

__device__ __forceinline__ void agg_load(int e, const int* __restrict__ ei,
                                         const float* __restrict__ eattr,
                                         int u0, EdgeData& d)
{
    d.ea = __ldg((const float4*)(eattr + (size_t)e * 4));
    int s = __ldg(ei + NEDGE + e);  // src = edge_index[1]
    const float* wr = g_w + (size_t)e * 512 + u0;
    d.wss = __ldg((const float4*)(wr));
    d.wsv = __ldg((const float4*)(wr + 128));
    d.wvs = __ldg((const float4*)(wr + 256));
    d.wvv = __ldg((const float4*)(wr + 384));
    d.xs  = __ldg((const float4*)(g_ys + (size_t)s * 128 + u0));
    const float* vb = g_yvt + (size_t)s * 128 + u0;
    d.x0 = __ldg((const float4*)(vb));
    d.x1 = __ldg((const float4*)(vb + NNODE * 128));
    d.x2 = __ldg((const float4*)(vb + 2 * NNODE * 128));
}

__device__ __forceinline__ void agg_accum(const EdgeData& d,
                                          float s0[4], float s1[4],
                                          float v2[3][4], float v3[3][4])
{
    const float inv_sq3 = 0.5773502691896258f;
    float as_ = d.ea.x, av0 = d.ea.y, av1 = d.ea.z, av2 = d.ea.w;
    float WSS[4] = {d.wss.x, d.wss.y, d.wss.z, d.wss.w};
    float WSV[4] = {d.wsv.x, d.wsv.y, d.wsv.z, d.wsv.w};
    float WVS[4] = {d.wvs.x, d.wvs.y, d.wvs.z, d.wvs.w};
    float WVV[4] = {d.wvv.x, d.wvv.y, d.wvv.z, d.wvv.w};
    float XS[4]  = {d.xs.x, d.xs.y, d.xs.z, d.xs.w};
    float X0[4]  = {d.x0.x, d.x0.y, d.x0.z, d.x0.w};
    float X1[4]  = {d.x1.x, d.x1.y, d.x1.z, d.x1.w};
    float X2[4]  = {d.x2.x, d.x2.y, d.x2.z, d.x2.w};
#pragma unroll
    for (int t = 0; t < 4; ++t) {
        s0[t] = fmaf(WSS[t] * as_, XS[t], s0[t]);
        float dot = X0[t] * av0 + X1[t] * av1 + X2[t] * av2;
        s1[t] = fmaf(WVV[t] * inv_sq3, dot, s1[t]);
        float tsv = WSV[t] * XS[t];
        v2[0][t] = fmaf(tsv, av0, v2[0][t]);
        v2[1][t] = fmaf(tsv, av1, v2[1][t]);
        v2[2][t] = fmaf(tsv, av2, v2[2][t]);
        float tvs = WVS[t] * as_;
        v3[0][t] = fmaf(tvs, X0[t], v3[0][t]);
        v3[1][t] = fmaf(tvs, X1[t], v3[1][t]);
        v3[2][t] = fmaf(tvs, X2[t], v3[2][t]);
    }
}

__global__ void __launch_bounds__(256) k_agg(const int* __restrict__ ei,
                                             const float* __restrict__ eattr)
{
    int gw = (blockIdx.x * blockDim.x + threadIdx.x) >> 5;
    int lane = threadIdx.x & 31;
    if (gw >= NNODE) return;
    const int n = gw;
    const int u0 = lane * 4;

    float s0[4] = {0, 0, 0, 0}, s1[4] = {0, 0, 0, 0};
    float v2[3][4] = {{0}}, v3[3][4] = {{0}};

    const int beg = g_rowstart[n];
    const int end = g_rowstart[n + 1];
    int i = beg;
    // 2-edge unroll: both edges' loads issue before either accumulation -> 2x MLP
    for (; i + 2 <= end; i += 2) {
        int e0 = __ldg(&g_eid[i]);
        int e1 = __ldg(&g_eid[i + 1]);
        EdgeData d0, d1;
        agg_load(e0, ei, eattr, u0, d0);
        agg_load(e1, ei, eattr, u0, d1);
        agg_accum(d0, s0, s1, v2, v3);
        agg_accum(d1, s0, s1, v2, v3);
    }
    if (i < end) {
        int e0 = __ldg(&g_eid[i]);
        EdgeData d0;
        agg_load(e0, ei, eattr, u0, d0);
        agg_accum(d0, s0, s1, v2, v3);
    }

    float* sp = g_aggs + (size_t)n * 256 + u0;
    *(float4*)(sp)       = make_float4(s0[0], s0[1], s0[2], s0[3]);
    *(float4*)(sp + 128) = make_float4(s1[0], s1[1], s1[2], s1[3]);
#pragma unroll
    for (int c = 0; c < 3; ++c) {
        float* vp = g_aggvt + (size_t)c * NNODE * 256 + (size_t)n * 256 + u0;
        *(float4*)(vp)       = make_float4(v2[c][0], v2[c][1], v2[c][2], v2[c][3]);
        *(float4*)(vp + 128) = make_float4(v3[c][0], v3[c][1], v3[c][2], v3[c][3]);
    }
}

// ---------------- launch -------------------------------------------------------
extern "C" void kernel_launch(void* const* d_in, const int* in_sizes, int n_in,
                              void* d_out, int out_size)
{
    const float* node_feats = (const float*)d_in[0];
    const float* node_attrs = (const float*)d_in[1];
    const float* edge_feats = (const float*)d_in[2];
    const float* edge_attrs = (const float*)d_in[3];
    const int*   edge_index = (const int*)d_in[4];
    const float* lin1_ws = (const float*)d_in[5];
    const float* lin1_wv = (const float*)d_in[6];
    const float* fc_w0   = (const float*)d_in[7];
    const float* fc_w1   = (const float*)d_in[8];
    const float* fc_w2   = (const float*)d_in[9];
    const float* lin2_ws = (const float*)d_in[10];
    const float* lin2_wv = (const float*)d_in[11];
    const float* sc_ws   = (const float*)d_in[12];
    const float* sc_wv   = (const float*)d_in[13];
    float* out = (float*)d_out;

    int* p_cnt;
    cudaGetSymbolAddress((void**)&p_cnt, g_cnt);

    // CSR build
    cudaMemsetAsync(p_cnt, 0, NNODE * sizeof(int));
    k_count<<<625, 256>>>(edge_index);
    k_scan<<<1, 256>>>();
    k_fill<<<625, 256>>>(edge_index);

    // fc small layers -> g_h
    k_fc01<<<2500, 128>>>(edge_feats, fc_w0, fc_w1);

    // ALL independent GEMMs in one launch (FFMA, register-pipelined):
    // [0,79) sc_s | [79,314) sc_v | [314,393) y_s | [393,628) y_v | [628,5628) w
    k_mega1<<<5628, 256>>>(node_feats, node_attrs, lin1_ws, lin1_wv,
                           sc_ws, sc_wv, fc_w2);

    // messages + segment sum (CSR, warp per node, 2-edge unrolled)
    k_agg<<<1250, 256>>>(edge_index, edge_attrs);

    // lin2 (s + v) + skip connection, writing packed output directly
    k_mega2<<<314, 256>>>(lin2_ws, lin2_wv, out);
}

// round 16
// speedup vs baseline: 1.0359x; 1.0232x over previous
#include <cuda_runtime.h>
#include <cstddef>

#define NNODE 10000
#define NEDGE 160000

// ---------------- scratch (static device globals; no allocation) ----------------
__device__ float g_h[NEDGE * 64];            // fc hidden, PERMUTED to CSR order
__device__ float g_w[NEDGE * 512];           // edge weights, indexed by CSR pos
__device__ float g_ea[NEDGE * 4];            // edge_attrs, permuted to CSR order
__device__ int   g_src[NEDGE];               // src node, permuted to CSR order
__device__ int   g_invp[NEDGE];              // e -> CSR position
__device__ float g_ys[NNODE * 128];          // y_s
__device__ float g_yvt[3 * NNODE * 128];     // y_v, [c][n][u]
__device__ float g_scs[NNODE * 128];         // sc_s
__device__ float g_scvt[3 * NNODE * 128];    // sc_v, [c][n][w]
__device__ float g_aggs[NNODE * 256];        // aggregated s (pre lin2)
__device__ float g_aggvt[3 * NNODE * 256];   // aggregated v, [c][n][p]
__device__ int   g_cnt[NNODE];
__device__ int   g_pos[NNODE];
__device__ int   g_rowstart[NNODE + 1];

#define L1S_C  0.08838834764831845f    // 1/sqrt(128)
#define SCN_C  0.027950849718747373f   // 1/sqrt(1280)
#define OUTA_C 0.015625f               // (1/sqrt(16)) * (1/sqrt(256))

// ---------------- A-element loader (templated synthesized views) ----------------
// AMODE 0: A[m*lda + k]
// AMODE 1: Z_s: node_feats[m*512 + k/10] * attrs[m*10 + k%10]
// AMODE 2: Z_v: rows m=(c*NNODE+n): node_feats[n*512+128+(k/10)*3+c]*attrs[n*10+k%10]
// AMODE 3: x_v: rows m=(c*NNODE+n): node_feats[n*512+128+k*3+c]
template <int AMODE>
__device__ __forceinline__ float loadA_elem(
    const float* __restrict__ A, const float* __restrict__ attrs,
    int m, int an, int ac, int kk, int lda, int M)
{
    if (m >= M) return 0.f;
    if (AMODE == 0) {
        return __ldg(A + (size_t)m * lda + kk);
    } else if (AMODE == 1) {
        int u = kk / 10, vv = kk - u * 10;
        return __ldg(A + (size_t)m * 512 + u) * __ldg(attrs + m * 10 + vv);
    } else if (AMODE == 2) {
        int u = kk / 10, vv = kk - u * 10;
        return __ldg(A + (size_t)an * 512 + 128 + u * 3 + ac) *
               __ldg(attrs + an * 10 + vv);
    } else {
        return __ldg(A + (size_t)an * 512 + 128 + kk * 3 + ac);
    }
}

// ---------------- SGEMM body, C = alpha * A@B (+ D) ----------------------------
// BM=BN=128, BK=8, 256 threads, 8x8 microtile, register-staged pipeline.
// OMODE 0: C[m*Ncols + col]
// OMODE 1: C[m*512 + col]               (packed out, scalar part)
// OMODE 2: C[n*512 + 128 + col*3 + c]   (packed out, vector part; m=c*NNODE+n)
template <int AMODE, int OMODE>
__device__ __forceinline__ void sgemm_body(
    float (*As)[128], float (*Bs)[128],
    int bx, int by,
    const float* __restrict__ A, const float* __restrict__ B,
    float* __restrict__ C, const float* __restrict__ D,
    const float* __restrict__ attrs,
    int M, int K, int Ncols, int lda, float alpha)
{
    const int tid = threadIdx.x;
    const int bm = by * 128;
    const int bn = bx * 128;
    const int tx = tid & 15;
    const int ty = tid >> 4;
    const int row0 = ty * 8;
    const int col0 = tx * 8;

    const int kA  = tid & 7;
    const int mA0 = tid >> 3;      // + 32*s
    const int nB  = tid & 127;
    const int kB0 = tid >> 7;      // + 2*s

    int mg[4], an[4], ac[4];
#pragma unroll
    for (int s = 0; s < 4; ++s) {
        int m = bm + mA0 + 32 * s;
        mg[s] = m;
        if (AMODE >= 2) {
            int c = m / NNODE;
            an[s] = m - c * NNODE;
            ac[s] = c;
        } else {
            an[s] = m; ac[s] = 0;
        }
    }

    float acc[8][8];
#pragma unroll
    for (int i = 0; i < 8; ++i)
#pragma unroll
        for (int j = 0; j < 8; ++j) acc[i][j] = 0.f;

    // prologue: prefetch tile k0=0 into registers
    float vA[4], vB[4];
#pragma unroll
    for (int s = 0; s < 4; ++s)
        vA[s] = loadA_elem<AMODE>(A, attrs, mg[s], an[s], ac[s], kA, lda, M);
#pragma unroll
    for (int s = 0; s < 4; ++s)
        vB[s] = __ldg(B + (size_t)(kB0 + 2 * s) * Ncols + bn + nB);

    for (int k0 = 0; k0 < K; k0 += 8) {
#pragma unroll
        for (int s = 0; s < 4; ++s) As[kA][mA0 + 32 * s] = vA[s];
#pragma unroll
        for (int s = 0; s < 4; ++s) Bs[kB0 + 2 * s][nB] = vB[s];
        __syncthreads();

        if (k0 + 8 < K) {   // next tile's loads hide under the FMA section
            int kn = k0 + 8;
#pragma unroll
            for (int s = 0; s < 4; ++s)
                vA[s] = loadA_elem<AMODE>(A, attrs, mg[s], an[s], ac[s],
                                          kn + kA, lda, M);
#pragma unroll
            for (int s = 0; s < 4; ++s)
                vB[s] = __ldg(B + (size_t)(kn + kB0 + 2 * s) * Ncols + bn + nB);
        }

#pragma unroll
        for (int k = 0; k < 8; ++k) {
            float4 a0 = *(const float4*)&As[k][row0];
            float4 a1 = *(const float4*)&As[k][row0 + 4];
            float4 b0 = *(const float4*)&Bs[k][col0];
            float4 b1 = *(const float4*)&Bs[k][col0 + 4];
            float a[8] = {a0.x, a0.y, a0.z, a0.w, a1.x, a1.y, a1.z, a1.w};
            float b[8] = {b0.x, b0.y, b0.z, b0.w, b1.x, b1.y, b1.z, b1.w};
#pragma unroll
            for (int i = 0; i < 8; ++i)
#pragma unroll
                for (int j = 0; j < 8; ++j)
                    acc[i][j] = fmaf(a[i], b[j], acc[i][j]);
        }
        __syncthreads();
    }

#pragma unroll
    for (int i = 0; i < 8; ++i) {
        int m = bm + row0 + i;
        if (m >= M) continue;
        float r[8];
#pragma unroll
        for (int j = 0; j < 8; ++j) r[j] = alpha * acc[i][j];
        if (D) {
            size_t doff = (size_t)m * Ncols + bn + col0;
            float4 d0 = __ldg((const float4*)(D + doff));
            float4 d1 = __ldg((const float4*)(D + doff + 4));
            r[0] += d0.x; r[1] += d0.y; r[2] += d0.z; r[3] += d0.w;
            r[4] += d1.x; r[5] += d1.y; r[6] += d1.z; r[7] += d1.w;
        }
        if (OMODE == 0) {
            size_t off = (size_t)m * Ncols + bn + col0;
            *(float4*)(C + off)     = make_float4(r[0], r[1], r[2], r[3]);
            *(float4*)(C + off + 4) = make_float4(r[4], r[5], r[6], r[7]);
        } else if (OMODE == 1) {
            float* base = C + (size_t)m * 512 + bn + col0;
            *(float4*)(base)     = make_float4(r[0], r[1], r[2], r[3]);
            *(float4*)(base + 4) = make_float4(r[4], r[5], r[6], r[7]);
        } else {
            int c = m / NNODE;
            int n = m - c * NNODE;
            float* base = C + (size_t)n * 512 + 128 + (size_t)(bn + col0) * 3 + c;
#pragma unroll
            for (int j = 0; j < 8; ++j) base[j * 3] = r[j];
        }
    }
}

// ---------------- merged GEMM launches ------------------------------------------
// mega1: long-K sc jobs first (LPT), then lin1, then 5000 w-GEMM blocks.
// g_h is CSR-permuted, so the w-GEMM is a plain contiguous GEMM and g_w comes
// out indexed by CSR position (contiguous reads in k_agg).
__global__ void __launch_bounds__(256) k_mega1(
    const float* __restrict__ nf, const float* __restrict__ attrs,
    const float* __restrict__ l1s, const float* __restrict__ l1v,
    const float* __restrict__ scw_s, const float* __restrict__ scw_v,
    const float* __restrict__ fcw2)
{
    __shared__ __align__(16) float As[8][128];
    __shared__ __align__(16) float Bs[8][128];
    int b = blockIdx.x;
    if (b < 79) {
        sgemm_body<1, 0>(As, Bs, 0, b, nf, scw_s, g_scs, nullptr, attrs,
                         NNODE, 1280, 128, 0, SCN_C);
    } else if (b < 314) {
        sgemm_body<2, 0>(As, Bs, 0, b - 79, nf, scw_v, g_scvt, nullptr, attrs,
                         3 * NNODE, 1280, 128, 0, SCN_C);
    } else if (b < 393) {
        sgemm_body<0, 0>(As, Bs, 0, b - 314, nf, l1s, g_ys, nullptr, nullptr,
                         NNODE, 128, 128, 512, L1S_C);
    } else if (b < 628) {
        sgemm_body<3, 0>(As, Bs, 0, b - 393, nf, l1v, g_yvt, nullptr, nullptr,
                         3 * NNODE, 128, 128, 0, L1S_C);
    } else {
        int l = b - 628;
        sgemm_body<0, 0>(As, Bs, l & 3, l >> 2, g_h, fcw2, g_w, nullptr, nullptr,
                         NEDGE, 64, 512, 64, 0.125f);
    }
}

// mega2: lin2 (s and v) with skip-connection, writing the packed output directly.
__global__ void __launch_bounds__(256) k_mega2(
    const float* __restrict__ l2s, const float* __restrict__ l2v,
    float* __restrict__ out)
{
    __shared__ __align__(16) float As[8][128];
    __shared__ __align__(16) float Bs[8][128];
    int b = blockIdx.x;
    if (b < 79) {
        sgemm_body<0, 1>(As, Bs, 0, b, g_aggs, l2s, out, g_scs, nullptr,
                         NNODE, 256, 128, 256, OUTA_C);
    } else {
        sgemm_body<0, 2>(As, Bs, 0, b - 79, g_aggvt, l2v, out, g_scvt, nullptr,
                         3 * NNODE, 256, 128, 256, OUTA_C);
    }
}

// ---------------- fc layers 0+1 (8->64->64, scaled SiLU, 1 MUFU per silu) ------
__device__ __forceinline__ float siluc(float x)
{
    float xc = fmaxf(x, -20.0f);
    float e = __expf(-xc);                 // 1 MUFU (EX2)
    float y = 1.0f + e;
    float r = __uint_as_float(0x7EF311C3u - __float_as_uint(y));  // rcp seed
    r = r * (2.0f - y * r);
    r = r * (2.0f - y * r);
    r = r * (2.0f - y * r);
    return 1.679f * x * r;
}

// writes g_h PERMUTED: row g_invp[e] holds edge e's hidden vector.
__global__ void __launch_bounds__(128) k_fc01(
    const float* __restrict__ ef, const float* __restrict__ w0,
    const float* __restrict__ w1)
{
    __shared__ __align__(16) float w0s[8 * 64];
    __shared__ __align__(16) float w1s[64 * 64];
    __shared__ float efs[64][9];
    __shared__ float h0s[64][66];
    const int tid = threadIdx.x;
    const float rs8 = 0.35355339059327373f;
    for (int i = tid; i < 8 * 64; i += 128) w0s[i] = w0[i] * rs8;
    for (int i = tid; i < 1024; i += 128) {
        float4 v = __ldg((const float4*)w1 + i);
        v.x *= 0.125f; v.y *= 0.125f; v.z *= 0.125f; v.w *= 0.125f;
        *(float4*)&w1s[i * 4] = v;
    }
    const int e0 = blockIdx.x * 64;
    {
        float4 v = __ldg((const float4*)(ef + (size_t)e0 * 8) + tid);
        int e = tid >> 1, k4 = (tid & 1) * 4;
        efs[e][k4 + 0] = v.x; efs[e][k4 + 1] = v.y;
        efs[e][k4 + 2] = v.z; efs[e][k4 + 3] = v.w;
    }
    __syncthreads();

    const int warp = tid >> 5, lane = tid & 31;
    const int j8 = (lane & 7) * 8;
    const int es = warp * 4 + (lane >> 3);
    const int eb = es * 4;

    float acc[4][8];
#pragma unroll
    for (int i = 0; i < 4; ++i)
#pragma unroll
        for (int j = 0; j < 8; ++j) acc[i][j] = 0.f;
#pragma unroll
    for (int k = 0; k < 8; ++k) {
        float4 wA = *(const float4*)&w0s[k * 64 + j8];
        float4 wB = *(const float4*)&w0s[k * 64 + j8 + 4];
        float wv[8] = {wA.x, wA.y, wA.z, wA.w, wB.x, wB.y, wB.z, wB.w};
#pragma unroll
        for (int i = 0; i < 4; ++i) {
            float a = efs[eb + i][k];
#pragma unroll
            for (int j = 0; j < 8; ++j) acc[i][j] = fmaf(a, wv[j], acc[i][j]);
        }
    }
#pragma unroll
    for (int i = 0; i < 4; ++i) {
#pragma unroll
        for (int j = 0; j < 8; j += 2) {
            float2 p = make_float2(siluc(acc[i][j]), siluc(acc[i][j + 1]));
            *(float2*)&h0s[eb + i][j8 + j] = p;
        }
    }
    __syncthreads();

#pragma unroll
    for (int i = 0; i < 4; ++i)
#pragma unroll
        for (int j = 0; j < 8; ++j) acc[i][j] = 0.f;
#pragma unroll 8
    for (int k = 0; k < 64; ++k) {
        float4 wA = *(const float4*)&w1s[k * 64 + j8];
        float4 wB = *(const float4*)&w1s[k * 64 + j8 + 4];
        float wv[8] = {wA.x, wA.y, wA.z, wA.w, wB.x, wB.y, wB.z, wB.w};
#pragma unroll
        for (int i = 0; i < 4; ++i) {
            float a = h0s[eb + i][k];
#pragma unroll
            for (int j = 0; j < 8; ++j) acc[i][j] = fmaf(a, wv[j], acc[i][j]);
        }
    }
#pragma unroll
    for (int i = 0; i < 4; ++i) {
        float o[8];
#pragma unroll
        for (int j = 0; j < 8; ++j) o[j] = siluc(acc[i][j]);
        int p = __ldg(&g_invp[e0 + eb + i]);
        float* dst = g_h + (size_t)p * 64 + j8;
        *(float4*)(dst)     = make_float4(o[0], o[1], o[2], o[3]);
        *(float4*)(dst + 4) = make_float4(o[4], o[5], o[6], o[7]);
    }
}

// ---------------- CSR build ----------------------------------------------------
__global__ void k_count(const int* __restrict__ ei)
{
    int e = blockIdx.x * 256 + threadIdx.x;
    if (e < NEDGE) atomicAdd(&g_cnt[ei[e]], 1);
}

__global__ void k_scan()
{
    __shared__ int sm[256];
    const int tid = threadIdx.x;
    const int CH = (NNODE + 255) / 256;
    int beg = tid * CH;
    int end = min(beg + CH, NNODE);
    int s = 0;
    for (int i = beg; i < end; ++i) s += g_cnt[i];
    sm[tid] = s;
    __syncthreads();
    for (int off = 1; off < 256; off <<= 1) {
        int v = 0;
        if (tid >= off) v = sm[tid - off];
        __syncthreads();
        sm[tid] += v;
        __syncthreads();
    }
    int run = sm[tid] - s;
    for (int i = beg; i < end; ++i) {
        g_rowstart[i] = run;
        g_pos[i] = run;
        run += g_cnt[i];
    }
    if (tid == 255) g_rowstart[NNODE] = sm[255];
}

// fill: assign CSR positions AND permute src/edge_attrs into CSR order.
__global__ void k_fill(const int* __restrict__ ei, const float* __restrict__ eattr)
{
    int e = blockIdx.x * 256 + threadIdx.x;
    if (e < NEDGE) {
        int d = __ldg(&ei[e]);
        int p = atomicAdd(&g_pos[d], 1);
        g_invp[e] = p;
        g_src[p] = __ldg(&ei[NEDGE + e]);
        ((float4*)g_ea)[p] = __ldg((const float4*)(eattr + (size_t)e * 4));
    }
}

// ---------------- message + aggregation: one warp per node, no float atomics ---
// All edge-side arrays (g_w, g_ea, g_src) are CSR-permuted -> fully contiguous
// streaming reads per node; no indirection loads.
struct EdgeData {
    float4 ea, wss, wsv, wvs, wvv, xs, x0, x1, x2;
};

__device__ __forceinline__ void agg_load(int p, int u0, EdgeData& d)
{
    d.ea = __ldg(&((const float4*)g_ea)[p]);
    int s = __ldg(&g_src[p]);
    const float* wr = g_w + (size_t)p * 512 + u0;
    d.wss = __ldg((const float4*)(wr));
    d.wsv = __ldg((const float4*)(wr + 128));
    d.wvs = __ldg((const float4*)(wr + 256));
    d.wvv = __ldg((const float4*)(wr + 384));
    d.xs  = __ldg((const float4*)(g_ys + (size_t)s * 128 + u0));
    const float* vb = g_yvt + (size_t)s * 128 + u0;
    d.x0 = __ldg((const float4*)(vb));
    d.x1 = __ldg((const float4*)(vb + NNODE * 128));
    d.x2 = __ldg((const float4*)(vb + 2 * NNODE * 128));
}

__device__ __forceinline__ void agg_accum(const EdgeData& d,
                                          float s0[4], float s1[4],
                                          float v2[3][4], float v3[3][4])
{
    const float inv_sq3 = 0.5773502691896258f;
    float as_ = d.ea.x, av0 = d.ea.y, av1 = d.ea.z, av2 = d.ea.w;
    float WSS[4] = {d.wss.x, d.wss.y, d.wss.z, d.wss.w};
    float WSV[4] = {d.wsv.x, d.wsv.y, d.wsv.z, d.wsv.w};
    float WVS[4] = {d.wvs.x, d.wvs.y, d.wvs.z, d.wvs.w};
    float WVV[4] = {d.wvv.x, d.wvv.y, d.wvv.z, d.wvv.w};
    float XS[4]  = {d.xs.x, d.xs.y, d.xs.z, d.xs.w};
    float X0[4]  = {d.x0.x, d.x0.y, d.x0.z, d.x0.w};
    float X1[4]  = {d.x1.x, d.x1.y, d.x1.z, d.x1.w};
    float X2[4]  = {d.x2.x, d.x2.y, d.x2.z, d.x2.w};
#pragma unroll
    for (int t = 0; t < 4; ++t) {
        s0[t] = fmaf(WSS[t] * as_, XS[t], s0[t]);
        float dot = X0[t] * av0 + X1[t] * av1 + X2[t] * av2;
        s1[t] = fmaf(WVV[t] * inv_sq3, dot, s1[t]);
        float tsv = WSV[t] * XS[t];
        v2[0][t] = fmaf(tsv, av0, v2[0][t]);
        v2[1][t] = fmaf(tsv, av1, v2[1][t]);
        v2[2][t] = fmaf(tsv, av2, v2[2][t]);
        float tvs = WVS[t] * as_;
        v3[0][t] = fmaf(tvs, X0[t], v3[0][t]);
        v3[1][t] = fmaf(tvs, X1[t], v3[1][t]);
        v3[2][t] = fmaf(tvs, X2[t], v3[2][t]);
    }
}

__global__ void __launch_bounds__(256) k_agg()
{
    int gw = (blockIdx.x * blockDim.x + threadIdx.x) >> 5;
    int lane = threadIdx.x & 31;
    if (gw >= NNODE) return;
    const int n = gw;
    const int u0 = lane * 4;

    float s0[4] = {0, 0, 0, 0}, s1[4] = {0, 0, 0, 0};
    float v2[3][4] = {{0}}, v3[3][4] = {{0}};

    const int beg = g_rowstart[n];
    const int end = g_rowstart[n + 1];
    int i = beg;
    for (; i + 2 <= end; i += 2) {
        EdgeData d0, d1;
        agg_load(i, u0, d0);
        agg_load(i + 1, u0, d1);
        agg_accum(d0, s0, s1, v2, v3);
        agg_accum(d1, s0, s1, v2, v3);
    }
    if (i < end) {
        EdgeData d0;
        agg_load(i, u0, d0);
        agg_accum(d0, s0, s1, v2, v3);
    }

    float* sp = g_aggs + (size_t)n * 256 + u0;
    *(float4*)(sp)       = make_float4(s0[0], s0[1], s0[2], s0[3]);
    *(float4*)(sp + 128) = make_float4(s1[0], s1[1], s1[2], s1[3]);
#pragma unroll
    for (int c = 0; c < 3; ++c) {
        float* vp = g_aggvt + (size_t)c * NNODE * 256 + (size_t)n * 256 + u0;
        *(float4*)(vp)       = make_float4(v2[c][0], v2[c][1], v2[c][2], v2[c][3]);
        *(float4*)(vp + 128) = make_float4(v3[c][0], v3[c][1], v3[c][2], v3[c][3]);
    }
}

// ---------------- launch -------------------------------------------------------
extern "C" void kernel_launch(void* const* d_in, const int* in_sizes, int n_in,
                              void* d_out, int out_size)
{
    const float* node_feats = (const float*)d_in[0];
    const float* node_attrs = (const float*)d_in[1];
    const float* edge_feats = (const float*)d_in[2];
    const float* edge_attrs = (const float*)d_in[3];
    const int*   edge_index = (const int*)d_in[4];
    const float* lin1_ws = (const float*)d_in[5];
    const float* lin1_wv = (const float*)d_in[6];
    const float* fc_w0   = (const float*)d_in[7];
    const float* fc_w1   = (const float*)d_in[8];
    const float* fc_w2   = (const float*)d_in[9];
    const float* lin2_ws = (const float*)d_in[10];
    const float* lin2_wv = (const float*)d_in[11];
    const float* sc_ws   = (const float*)d_in[12];
    const float* sc_wv   = (const float*)d_in[13];
    float* out = (float*)d_out;

    int* p_cnt;
    cudaGetSymbolAddress((void**)&p_cnt, g_cnt);

    // CSR build + edge permutation
    cudaMemsetAsync(p_cnt, 0, NNODE * sizeof(int));
    k_count<<<625, 256>>>(edge_index);
    k_scan<<<1, 256>>>();
    k_fill<<<625, 256>>>(edge_index, edge_attrs);

    // fc small layers -> g_h (CSR-permuted rows)
    k_fc01<<<2500, 128>>>(edge_feats, fc_w0, fc_w1);

    // ALL independent GEMMs in one launch (FFMA, register-pipelined):
    // [0,79) sc_s | [79,314) sc_v | [314,393) y_s | [393,628) y_v | [628,5628) w
    k_mega1<<<5628, 256>>>(node_feats, node_attrs, lin1_ws, lin1_wv,
                           sc_ws, sc_wv, fc_w2);

    // messages + segment sum: fully contiguous per-node streams
    k_agg<<<1250, 256>>>();

    // lin2 (s + v) + skip connection, writing packed output directly
    k_mega2<<<314, 256>>>(lin2_ws, lin2_wv, out);
}

// round 17
// speedup vs baseline: 1.0516x; 1.0152x over previous
#include <cuda_runtime.h>
#include <cstddef>

#define NNODE 10000
#define NEDGE 160000

// ---------------- scratch (static device globals; no allocation) ----------------
__device__ float g_h[NEDGE * 64];            // fc hidden, PERMUTED to CSR order
__device__ float g_w[NEDGE * 512];           // edge weights, indexed by CSR pos
__device__ float g_ea[NEDGE * 4];            // edge_attrs, permuted to CSR order
__device__ int   g_src[NEDGE];               // src node, permuted to CSR order
__device__ int   g_invp[NEDGE];              // e -> CSR position
__device__ float g_ys[NNODE * 128];          // y_s
__device__ float g_yvt[3 * NNODE * 128];     // y_v, [c][n][u]
__device__ float g_scs[NNODE * 128];         // sc_s
__device__ float g_scvt[3 * NNODE * 128];    // sc_v, [c][n][w]
__device__ float g_aggs[NNODE * 256];        // aggregated s (pre lin2)
__device__ float g_aggvt[3 * NNODE * 256];   // aggregated v, [c][n][p]
__device__ int   g_cnt[NNODE];
__device__ int   g_pos[NNODE];
__device__ int   g_rowstart[NNODE + 1];

#define L1S_C  0.08838834764831845f    // 1/sqrt(128)
#define SCN_C  0.027950849718747373f   // 1/sqrt(1280)
#define OUTA_C 0.015625f               // (1/sqrt(16)) * (1/sqrt(256))

// ---------------- A-element loader (templated synthesized views) ----------------
// AMODE 0: A[m*lda + k]
// AMODE 1: Z_s: node_feats[m*512 + k/10] * attrs[m*10 + k%10]
// AMODE 2: Z_v: rows m=(c*NNODE+n): node_feats[n*512+128+(k/10)*3+c]*attrs[n*10+k%10]
// AMODE 3: x_v: rows m=(c*NNODE+n): node_feats[n*512+128+k*3+c]
template <int AMODE>
__device__ __forceinline__ float loadA_elem(
    const float* __restrict__ A, const float* __restrict__ attrs,
    int m, int an, int ac, int kk, int lda, int M)
{
    if (m >= M) return 0.f;
    if (AMODE == 0) {
        return __ldg(A + (size_t)m * lda + kk);
    } else if (AMODE == 1) {
        int u = kk / 10, vv = kk - u * 10;
        return __ldg(A + (size_t)m * 512 + u) * __ldg(attrs + m * 10 + vv);
    } else if (AMODE == 2) {
        int u = kk / 10, vv = kk - u * 10;
        return __ldg(A + (size_t)an * 512 + 128 + u * 3 + ac) *
               __ldg(attrs + an * 10 + vv);
    } else {
        return __ldg(A + (size_t)an * 512 + 128 + kk * 3 + ac);
    }
}

// ---------------- SGEMM body, C = alpha * A@B (+ D) ----------------------------
// BM=BN=128, BK=8, 256 threads, 8x8 microtile, register-staged pipeline.
// OMODE 0: C[m*Ncols + col]
// OMODE 1: C[m*512 + col]               (packed out, scalar part)
// OMODE 2: C[n*512 + 128 + col*3 + c]   (packed out, vector part; m=c*NNODE+n)
template <int AMODE, int OMODE>
__device__ __forceinline__ void sgemm_body(
    float (*As)[128], float (*Bs)[128],
    int bx, int by,
    const float* __restrict__ A, const float* __restrict__ B,
    float* __restrict__ C, const float* __restrict__ D,
    const float* __restrict__ attrs,
    int M, int K, int Ncols, int lda, float alpha)
{
    const int tid = threadIdx.x;
    const int bm = by * 128;
    const int bn = bx * 128;
    const int tx = tid & 15;
    const int ty = tid >> 4;
    const int row0 = ty * 8;
    const int col0 = tx * 8;

    const int kA  = tid & 7;
    const int mA0 = tid >> 3;      // + 32*s
    const int nB  = tid & 127;
    const int kB0 = tid >> 7;      // + 2*s

    int mg[4], an[4], ac[4];
#pragma unroll
    for (int s = 0; s < 4; ++s) {
        int m = bm + mA0 + 32 * s;
        mg[s] = m;
        if (AMODE >= 2) {
            int c = m / NNODE;
            an[s] = m - c * NNODE;
            ac[s] = c;
        } else {
            an[s] = m; ac[s] = 0;
        }
    }

    float acc[8][8];
#pragma unroll
    for (int i = 0; i < 8; ++i)
#pragma unroll
        for (int j = 0; j < 8; ++j) acc[i][j] = 0.f;

    // prologue: prefetch tile k0=0 into registers
    float vA[4], vB[4];
#pragma unroll
    for (int s = 0; s < 4; ++s)
        vA[s] = loadA_elem<AMODE>(A, attrs, mg[s], an[s], ac[s], kA, lda, M);
#pragma unroll
    for (int s = 0; s < 4; ++s)
        vB[s] = __ldg(B + (size_t)(kB0 + 2 * s) * Ncols + bn + nB);

    for (int k0 = 0; k0 < K; k0 += 8) {
#pragma unroll
        for (int s = 0; s < 4; ++s) As[kA][mA0 + 32 * s] = vA[s];
#pragma unroll
        for (int s = 0; s < 4; ++s) Bs[kB0 + 2 * s][nB] = vB[s];
        __syncthreads();

        if (k0 + 8 < K) {   // next tile's loads hide under the FMA section
            int kn = k0 + 8;
#pragma unroll
            for (int s = 0; s < 4; ++s)
                vA[s] = loadA_elem<AMODE>(A, attrs, mg[s], an[s], ac[s],
                                          kn + kA, lda, M);
#pragma unroll
            for (int s = 0; s < 4; ++s)
                vB[s] = __ldg(B + (size_t)(kn + kB0 + 2 * s) * Ncols + bn + nB);
        }

#pragma unroll
        for (int k = 0; k < 8; ++k) {
            float4 a0 = *(const float4*)&As[k][row0];
            float4 a1 = *(const float4*)&As[k][row0 + 4];
            float4 b0 = *(const float4*)&Bs[k][col0];
            float4 b1 = *(const float4*)&Bs[k][col0 + 4];
            float a[8] = {a0.x, a0.y, a0.z, a0.w, a1.x, a1.y, a1.z, a1.w};
            float b[8] = {b0.x, b0.y, b0.z, b0.w, b1.x, b1.y, b1.z, b1.w};
#pragma unroll
            for (int i = 0; i < 8; ++i)
#pragma unroll
                for (int j = 0; j < 8; ++j)
                    acc[i][j] = fmaf(a[i], b[j], acc[i][j]);
        }
        __syncthreads();
    }

#pragma unroll
    for (int i = 0; i < 8; ++i) {
        int m = bm + row0 + i;
        if (m >= M) continue;
        float r[8];
#pragma unroll
        for (int j = 0; j < 8; ++j) r[j] = alpha * acc[i][j];
        if (D) {
            size_t doff = (size_t)m * Ncols + bn + col0;
            float4 d0 = __ldg((const float4*)(D + doff));
            float4 d1 = __ldg((const float4*)(D + doff + 4));
            r[0] += d0.x; r[1] += d0.y; r[2] += d0.z; r[3] += d0.w;
            r[4] += d1.x; r[5] += d1.y; r[6] += d1.z; r[7] += d1.w;
        }
        if (OMODE == 0) {
            size_t off = (size_t)m * Ncols + bn + col0;
            *(float4*)(C + off)     = make_float4(r[0], r[1], r[2], r[3]);
            *(float4*)(C + off + 4) = make_float4(r[4], r[5], r[6], r[7]);
        } else if (OMODE == 1) {
            float* base = C + (size_t)m * 512 + bn + col0;
            *(float4*)(base)     = make_float4(r[0], r[1], r[2], r[3]);
            *(float4*)(base + 4) = make_float4(r[4], r[5], r[6], r[7]);
        } else {
            int c = m / NNODE;
            int n = m - c * NNODE;
            float* base = C + (size_t)n * 512 + 128 + (size_t)(bn + col0) * 3 + c;
#pragma unroll
            for (int j = 0; j < 8; ++j) base[j * 3] = r[j];
        }
    }
}

// ---------------- merged GEMM launches ------------------------------------------
__global__ void __launch_bounds__(256) k_mega1(
    const float* __restrict__ nf, const float* __restrict__ attrs,
    const float* __restrict__ l1s, const float* __restrict__ l1v,
    const float* __restrict__ scw_s, const float* __restrict__ scw_v,
    const float* __restrict__ fcw2)
{
    __shared__ __align__(16) float As[8][128];
    __shared__ __align__(16) float Bs[8][128];
    int b = blockIdx.x;
    if (b < 79) {
        sgemm_body<1, 0>(As, Bs, 0, b, nf, scw_s, g_scs, nullptr, attrs,
                         NNODE, 1280, 128, 0, SCN_C);
    } else if (b < 314) {
        sgemm_body<2, 0>(As, Bs, 0, b - 79, nf, scw_v, g_scvt, nullptr, attrs,
                         3 * NNODE, 1280, 128, 0, SCN_C);
    } else if (b < 393) {
        sgemm_body<0, 0>(As, Bs, 0, b - 314, nf, l1s, g_ys, nullptr, nullptr,
                         NNODE, 128, 128, 512, L1S_C);
    } else if (b < 628) {
        sgemm_body<3, 0>(As, Bs, 0, b - 393, nf, l1v, g_yvt, nullptr, nullptr,
                         3 * NNODE, 128, 128, 0, L1S_C);
    } else {
        int l = b - 628;
        sgemm_body<0, 0>(As, Bs, l & 3, l >> 2, g_h, fcw2, g_w, nullptr, nullptr,
                         NEDGE, 64, 512, 64, 0.125f);
    }
}

__global__ void __launch_bounds__(256) k_mega2(
    const float* __restrict__ l2s, const float* __restrict__ l2v,
    float* __restrict__ out)
{
    __shared__ __align__(16) float As[8][128];
    __shared__ __align__(16) float Bs[8][128];
    int b = blockIdx.x;
    if (b < 79) {
        sgemm_body<0, 1>(As, Bs, 0, b, g_aggs, l2s, out, g_scs, nullptr,
                         NNODE, 256, 128, 256, OUTA_C);
    } else {
        sgemm_body<0, 2>(As, Bs, 0, b - 79, g_aggvt, l2v, out, g_scvt, nullptr,
                         3 * NNODE, 256, 128, 256, OUTA_C);
    }
}

// ---------------- fc layers 0+1 (8->64->64, scaled SiLU, 1 MUFU per silu) ------
__device__ __forceinline__ float siluc(float x)
{
    float xc = fmaxf(x, -20.0f);
    float e = __expf(-xc);                 // 1 MUFU (EX2)
    float y = 1.0f + e;
    float r = __uint_as_float(0x7EF311C3u - __float_as_uint(y));  // rcp seed
    r = r * (2.0f - y * r);
    r = r * (2.0f - y * r);
    r = r * (2.0f - y * r);
    return 1.679f * x * r;
}

// writes g_h PERMUTED: row g_invp[e] holds edge e's hidden vector.
// Layer 1 reads activations as LDS.128 (4 k's per load): h0s padded to 68.
__global__ void __launch_bounds__(128) k_fc01(
    const float* __restrict__ ef, const float* __restrict__ w0,
    const float* __restrict__ w1)
{
    __shared__ __align__(16) float w0s[8 * 64];
    __shared__ __align__(16) float w1s[64 * 64];
    __shared__ float efs[64][9];
    __shared__ __align__(16) float h0s[64][68];   // 68: 16B-aligned rows, no conflicts
    const int tid = threadIdx.x;
    const float rs8 = 0.35355339059327373f;
    for (int i = tid; i < 8 * 64; i += 128) w0s[i] = w0[i] * rs8;
    for (int i = tid; i < 1024; i += 128) {
        float4 v = __ldg((const float4*)w1 + i);
        v.x *= 0.125f; v.y *= 0.125f; v.z *= 0.125f; v.w *= 0.125f;
        *(float4*)&w1s[i * 4] = v;
    }
    const int e0 = blockIdx.x * 64;
    {
        float4 v = __ldg((const float4*)(ef + (size_t)e0 * 8) + tid);
        int e = tid >> 1, k4 = (tid & 1) * 4;
        efs[e][k4 + 0] = v.x; efs[e][k4 + 1] = v.y;
        efs[e][k4 + 2] = v.z; efs[e][k4 + 3] = v.w;
    }
    __syncthreads();

    const int warp = tid >> 5, lane = tid & 31;
    const int j8 = (lane & 7) * 8;
    const int es = warp * 4 + (lane >> 3);
    const int eb = es * 4;

    float acc[4][8];
#pragma unroll
    for (int i = 0; i < 4; ++i)
#pragma unroll
        for (int j = 0; j < 8; ++j) acc[i][j] = 0.f;
#pragma unroll
    for (int k = 0; k < 8; ++k) {
        float4 wA = *(const float4*)&w0s[k * 64 + j8];
        float4 wB = *(const float4*)&w0s[k * 64 + j8 + 4];
        float wv[8] = {wA.x, wA.y, wA.z, wA.w, wB.x, wB.y, wB.z, wB.w};
#pragma unroll
        for (int i = 0; i < 4; ++i) {
            float a = efs[eb + i][k];
#pragma unroll
            for (int j = 0; j < 8; ++j) acc[i][j] = fmaf(a, wv[j], acc[i][j]);
        }
    }
#pragma unroll
    for (int i = 0; i < 4; ++i) {
#pragma unroll
        for (int j = 0; j < 8; j += 2) {
            float2 p = make_float2(siluc(acc[i][j]), siluc(acc[i][j + 1]));
            *(float2*)&h0s[eb + i][j8 + j] = p;
        }
    }
    __syncthreads();

    // layer 1: 64 -> 64, activations via LDS.128 (4 k per load per edge)
#pragma unroll
    for (int i = 0; i < 4; ++i)
#pragma unroll
        for (int j = 0; j < 8; ++j) acc[i][j] = 0.f;
#pragma unroll 4
    for (int k4 = 0; k4 < 16; ++k4) {
        float4 a4[4];
#pragma unroll
        for (int i = 0; i < 4; ++i)
            a4[i] = *(const float4*)&h0s[eb + i][k4 * 4];
#pragma unroll
        for (int kk = 0; kk < 4; ++kk) {
            int k = k4 * 4 + kk;
            float4 wA = *(const float4*)&w1s[k * 64 + j8];
            float4 wB = *(const float4*)&w1s[k * 64 + j8 + 4];
            float wv[8] = {wA.x, wA.y, wA.z, wA.w, wB.x, wB.y, wB.z, wB.w};
#pragma unroll
            for (int i = 0; i < 4; ++i) {
                const float* ap = (const float*)&a4[i];
                float a = ap[kk];
#pragma unroll
                for (int j = 0; j < 8; ++j) acc[i][j] = fmaf(a, wv[j], acc[i][j]);
            }
        }
    }
#pragma unroll
    for (int i = 0; i < 4; ++i) {
        float o[8];
#pragma unroll
        for (int j = 0; j < 8; ++j) o[j] = siluc(acc[i][j]);
        int p = __ldg(&g_invp[e0 + eb + i]);
        float* dst = g_h + (size_t)p * 64 + j8;
        *(float4*)(dst)     = make_float4(o[0], o[1], o[2], o[3]);
        *(float4*)(dst + 4) = make_float4(o[4], o[5], o[6], o[7]);
    }
}

// ---------------- CSR build ----------------------------------------------------
__global__ void k_count(const int* __restrict__ ei)
{
    int e = blockIdx.x * 256 + threadIdx.x;
    if (e < NEDGE) atomicAdd(&g_cnt[ei[e]], 1);
}

__global__ void k_scan()
{
    __shared__ int sm[256];
    const int tid = threadIdx.x;
    const int CH = (NNODE + 255) / 256;
    int beg = tid * CH;
    int end = min(beg + CH, NNODE);
    int s = 0;
    for (int i = beg; i < end; ++i) s += g_cnt[i];
    sm[tid] = s;
    __syncthreads();
    for (int off = 1; off < 256; off <<= 1) {
        int v = 0;
        if (tid >= off) v = sm[tid - off];
        __syncthreads();
        sm[tid] += v;
        __syncthreads();
    }
    int run = sm[tid] - s;
    for (int i = beg; i < end; ++i) {
        g_rowstart[i] = run;
        g_pos[i] = run;
        run += g_cnt[i];
    }
    if (tid == 255) g_rowstart[NNODE] = sm[255];
}

// fill: assign CSR positions AND permute src/edge_attrs into CSR order.
__global__ void k_fill(const int* __restrict__ ei, const float* __restrict__ eattr)
{
    int e = blockIdx.x * 256 + threadIdx.x;
    if (e < NEDGE) {
        int d = __ldg(&ei[e]);
        int p = atomicAdd(&g_pos[d], 1);
        g_invp[e] = p;
        g_src[p] = __ldg(&ei[NEDGE + e]);
        ((float4*)g_ea)[p] = __ldg((const float4*)(eattr + (size_t)e * 4));
    }
}

// ---------------- message + aggregation: TWO warps per node --------------------
// Each node split across a warp pair (even/odd CSR positions) -> half the serial
// load-latency chain per warp, 2x warp parallelism. Odd warp's partials combined
// through padded smem. All edge arrays CSR-permuted -> contiguous streams.
struct EdgeData {
    float4 ea, wss, wsv, wvs, wvv, xs, x0, x1, x2;
};

__device__ __forceinline__ void agg_load(int p, int u0, EdgeData& d)
{
    d.ea = __ldg(&((const float4*)g_ea)[p]);
    int s = __ldg(&g_src[p]);
    const float* wr = g_w + (size_t)p * 512 + u0;
    d.wss = __ldg((const float4*)(wr));
    d.wsv = __ldg((const float4*)(wr + 128));
    d.wvs = __ldg((const float4*)(wr + 256));
    d.wvv = __ldg((const float4*)(wr + 384));
    d.xs  = __ldg((const float4*)(g_ys + (size_t)s * 128 + u0));
    const float* vb = g_yvt + (size_t)s * 128 + u0;
    d.x0 = __ldg((const float4*)(vb));
    d.x1 = __ldg((const float4*)(vb + NNODE * 128));
    d.x2 = __ldg((const float4*)(vb + 2 * NNODE * 128));
}

__device__ __forceinline__ void agg_accum(const EdgeData& d, float* v)
{
    // v layout: [0:4) s0 | [4:8) s1 | [8:20) v2[c][t] | [20:32) v3[c][t]
    const float inv_sq3 = 0.5773502691896258f;
    float as_ = d.ea.x, av0 = d.ea.y, av1 = d.ea.z, av2 = d.ea.w;
    float WSS[4] = {d.wss.x, d.wss.y, d.wss.z, d.wss.w};
    float WSV[4] = {d.wsv.x, d.wsv.y, d.wsv.z, d.wsv.w};
    float WVS[4] = {d.wvs.x, d.wvs.y, d.wvs.z, d.wvs.w};
    float WVV[4] = {d.wvv.x, d.wvv.y, d.wvv.z, d.wvv.w};
    float XS[4]  = {d.xs.x, d.xs.y, d.xs.z, d.xs.w};
    float X0[4]  = {d.x0.x, d.x0.y, d.x0.z, d.x0.w};
    float X1[4]  = {d.x1.x, d.x1.y, d.x1.z, d.x1.w};
    float X2[4]  = {d.x2.x, d.x2.y, d.x2.z, d.x2.w};
#pragma unroll
    for (int t = 0; t < 4; ++t) {
        v[t] = fmaf(WSS[t] * as_, XS[t], v[t]);
        float dot = X0[t] * av0 + X1[t] * av1 + X2[t] * av2;
        v[4 + t] = fmaf(WVV[t] * inv_sq3, dot, v[4 + t]);
        float tsv = WSV[t] * XS[t];
        v[8 + t]  = fmaf(tsv, av0, v[8 + t]);
        v[12 + t] = fmaf(tsv, av1, v[12 + t]);
        v[16 + t] = fmaf(tsv, av2, v[16 + t]);
        float tvs = WVS[t] * as_;
        v[20 + t] = fmaf(tvs, X0[t], v[20 + t]);
        v[24 + t] = fmaf(tvs, X1[t], v[24 + t]);
        v[28 + t] = fmaf(tvs, X2[t], v[28 + t]);
    }
}

__global__ void __launch_bounds__(256) k_agg()
{
    __shared__ float part[4][32][33];   // odd-warp partials, padded (bank-free)
    const int wid = threadIdx.x >> 5;   // 0..7
    const int lane = threadIdx.x & 31;
    const int gw = blockIdx.x * 8 + wid;   // 0..19999 (grid=2500)
    const int n = gw >> 1;
    const int half = gw & 1;
    const int pid = wid >> 1;
    const int u0 = lane * 4;

    float v[32];
#pragma unroll
    for (int j = 0; j < 32; ++j) v[j] = 0.f;

    const int beg = g_rowstart[n];
    const int end = g_rowstart[n + 1];
    int i = beg + half;
    if (i < end) {
        EdgeData d0;
        agg_load(i, u0, d0);
        for (i += 2; i < end; i += 2) {
            EdgeData d1;
            agg_load(i, u0, d1);      // prefetch next while accumulating current
            agg_accum(d0, v);
            d0 = d1;
        }
        agg_accum(d0, v);
    }

    if (half) {
#pragma unroll
        for (int j = 0; j < 32; ++j) part[pid][lane][j] = v[j];
    }
    __syncthreads();
    if (half) return;

#pragma unroll
    for (int j = 0; j < 32; ++j) v[j] += part[pid][lane][j];

    float* sp = g_aggs + (size_t)n * 256 + u0;
    *(float4*)(sp)       = make_float4(v[0], v[1], v[2], v[3]);
    *(float4*)(sp + 128) = make_float4(v[4], v[5], v[6], v[7]);
#pragma unroll
    for (int c = 0; c < 3; ++c) {
        float* vp = g_aggvt + (size_t)c * NNODE * 256 + (size_t)n * 256 + u0;
        *(float4*)(vp)       = make_float4(v[8 + 4 * c + 0], v[8 + 4 * c + 1],
                                           v[8 + 4 * c + 2], v[8 + 4 * c + 3]);
        *(float4*)(vp + 128) = make_float4(v[20 + 4 * c + 0], v[20 + 4 * c + 1],
                                           v[20 + 4 * c + 2], v[20 + 4 * c + 3]);
    }
}

// ---------------- launch -------------------------------------------------------
extern "C" void kernel_launch(void* const* d_in, const int* in_sizes, int n_in,
                              void* d_out, int out_size)
{
    const float* node_feats = (const float*)d_in[0];
    const float* node_attrs = (const float*)d_in[1];
    const float* edge_feats = (const float*)d_in[2];
    const float* edge_attrs = (const float*)d_in[3];
    const int*   edge_index = (const int*)d_in[4];
    const float* lin1_ws = (const float*)d_in[5];
    const float* lin1_wv = (const float*)d_in[6];
    const float* fc_w0   = (const float*)d_in[7];
    const float* fc_w1   = (const float*)d_in[8];
    const float* fc_w2   = (const float*)d_in[9];
    const float* lin2_ws = (const float*)d_in[10];
    const float* lin2_wv = (const float*)d_in[11];
    const float* sc_ws   = (const float*)d_in[12];
    const float* sc_wv   = (const float*)d_in[13];
    float* out = (float*)d_out;

    int* p_cnt;
    cudaGetSymbolAddress((void**)&p_cnt, g_cnt);

    // CSR build + edge permutation
    cudaMemsetAsync(p_cnt, 0, NNODE * sizeof(int));
    k_count<<<625, 256>>>(edge_index);
    k_scan<<<1, 256>>>();
    k_fill<<<625, 256>>>(edge_index, edge_attrs);

    // fc small layers -> g_h (CSR-permuted rows)
    k_fc01<<<2500, 128>>>(edge_feats, fc_w0, fc_w1);

    // ALL independent GEMMs in one launch (FFMA, register-pipelined):
    // [0,79) sc_s | [79,314) sc_v | [314,393) y_s | [393,628) y_v | [628,5628) w
    k_mega1<<<5628, 256>>>(node_feats, node_attrs, lin1_ws, lin1_wv,
                           sc_ws, sc_wv, fc_w2);

    // messages + segment sum: 2 warps per node, contiguous streams
    k_agg<<<2500, 256>>>();

    // lin2 (s + v) + skip connection, writing packed output directly
    k_mega2<<<314, 256>>>(lin2_ws, lin2_wv, out);
}